// round 15
// baseline (speedup 1.0000x reference)
#include <cuda_runtime.h>
#include <cuda_bf16.h>

#define T_ 4
#define B_ 16
#define C_ 512
#define N_ 1024
#define H_ 8
#define TB_ (T_ * B_)
#define CN_ (C_ * N_)                      // 524288
#define BCN_ ((size_t)B_ * CN_)            // 8388608
#define TBCN_ ((size_t)T_ * B_ * CN_)      // 33554432

// ---------------- scratch (device globals; allocations forbidden) -----------
__device__ float g_yq[TBCN_];
__device__ float g_yk[TBCN_];
__device__ float g_yv[TBCN_];   // reused for proj conv output
__device__ float g_x[TBCN_];
__device__ unsigned char g_qs[TBCN_];
__device__ unsigned char g_ks[TBCN_];
__device__ unsigned char g_vs2[TBCN_];
__device__ unsigned char g_xs[TBCN_];
__device__ float g_vst[BCN_];
__device__ float g_mean[4 * C_];
__device__ float g_rstd[4 * C_];
__device__ unsigned int g_Mq[(size_t)TB_ * N_ * 16];   // column bitmasks, 4MB
__device__ unsigned int g_Mk[(size_t)TB_ * N_ * 16];
__device__ unsigned int g_Mx[(size_t)TB_ * N_ * 16];
__device__ unsigned short g_Lx[(size_t)TB_ * N_ * 512];  // xs index lists, 64MB
__device__ int g_cntx[TB_ * N_];

// LIF membrane update: rn(v + rn(x - v)/2) — bit-exact vs reference.
__device__ __forceinline__ float lif_up(float v, float x) {
    return __fmaf_rn(__fsub_rn(x, v), 0.5f, v);
}

// Packed f32x2 add, per-component round-to-nearest == two scalar __fadd_rn.
__device__ __forceinline__ unsigned long long add2(unsigned long long a,
                                                   unsigned long long b) {
    unsigned long long r;
    asm("add.rn.f32x2 %0, %1, %2;" : "=l"(r) : "l"(a), "l"(b));
    return r;
}

// =============================================================================
// LIF over q and k simultaneously (vs == ks in the reference; keep k membrane)
// =============================================================================
__global__ __launch_bounds__(256) void k_lif_qk(const float* __restrict__ q,
                                                const float* __restrict__ k) {
    size_t i = (size_t)blockIdx.x * 256 + threadIdx.x;
    if (i >= BCN_) return;
    float vq = 0.0f, vk = 0.0f;
#pragma unroll
    for (int t = 0; t < T_; t++) {
        size_t off = (size_t)t * BCN_ + i;
        vq = lif_up(vq, q[off]);
        unsigned char s = (vq >= 1.0f) ? 1 : 0;
        g_qs[off] = s;
        if (s) vq = 0.0f;
        vk = lif_up(vk, k[off]);
        s = (vk >= 1.0f) ? 1 : 0;
        g_ks[off] = s;
        if (s) vk = 0.0f;
    }
    g_vst[i] = vk;
}

// =============================================================================
// Build per-column channel bitmasks for qs and ks spikes.
// =============================================================================
__global__ __launch_bounds__(256) void k_bitmask() {
    const int tb = blockIdx.y;
    const int n = blockIdx.x * 256 + threadIdx.x;
    const unsigned char* Sq = g_qs + (size_t)tb * CN_ + n;
    const unsigned char* Sk = g_ks + (size_t)tb * CN_ + n;
    unsigned int* Mq = g_Mq + ((size_t)tb * N_ + n) * 16;
    unsigned int* Mk = g_Mk + ((size_t)tb * N_ + n) * 16;
#pragma unroll
    for (int w = 0; w < 16; w++) {
        unsigned int mq = 0, mk = 0;
#pragma unroll
        for (int j = 0; j < 32; j++) {
            int c = w * 32 + j;
            mq |= ((unsigned int)Sq[(size_t)c * N_]) << j;
            mk |= ((unsigned int)Sk[(size_t)c * N_]) << j;
        }
        Mq[w] = mq;
        Mk[w] = mk;
    }
}

// Bitmask for xs spikes (proj conv input).
__global__ __launch_bounds__(256) void k_bitmask_x() {
    const int tb = blockIdx.y;
    const int n = blockIdx.x * 256 + threadIdx.x;
    const unsigned char* S = g_xs + (size_t)tb * CN_ + n;
    unsigned int* Mx = g_Mx + ((size_t)tb * N_ + n) * 16;
#pragma unroll
    for (int w = 0; w < 16; w++) {
        unsigned int m = 0;
#pragma unroll
        for (int j = 0; j < 32; j++)
            m |= ((unsigned int)S[(size_t)(w * 32 + j) * N_]) << j;
        Mx[w] = m;
    }
}

// =============================================================================
// Build ascending-c index lists for xs columns (global, stride 512).
// Block = 64 columns (8 warps x 8 cols, 4 lanes/col); smem staging + coalesced
// copy-out.
// =============================================================================
__global__ __launch_bounds__(256) void k_lists_x() {
    extern __shared__ unsigned short sl[];   // [64][512] = 64KB
    const int tb = blockIdx.y;
    const int nb = blockIdx.x * 64;
    const int tid = threadIdx.x;
    const int lane = tid & 31, wid = tid >> 5;
    const int col = wid * 8 + (lane >> 2);   // 0..63 local
    const int seg = lane & 3;
    const int n = nb + col;

    uint4 mm = *(const uint4*)(g_Mx + ((size_t)tb * N_ + n) * 16 + seg * 4);
    int pc = __popc(mm.x) + __popc(mm.y) + __popc(mm.z) + __popc(mm.w);
    int s = pc, t;
    t = __shfl_up_sync(0xFFFFFFFFu, s, 1); if (seg >= 1) s += t;
    t = __shfl_up_sync(0xFFFFFFFFu, s, 2); if (seg >= 2) s += t;
    int pos = s - pc;
    {
        unsigned short* L = sl + col * 512;
        unsigned int mw_[4] = {mm.x, mm.y, mm.z, mm.w};
#pragma unroll
        for (int w = 0; w < 4; w++) {
            unsigned int m = mw_[w];
            const int cb = seg * 128 + w * 32;
            while (m) {
                int j = __ffs((int)m) - 1;
                m &= m - 1;
                L[pos++] = (unsigned short)(cb + j);
            }
        }
    }
    if (seg == 3) g_cntx[tb * N_ + n] = s;
    __syncthreads();

    // coalesced copy-out: 64*512 uint16 = 4096 uint4
    unsigned short* dst = g_Lx + ((size_t)tb * N_ + nb) * 512;
    for (int i = tid; i < 4096; i += 256)
        ((uint4*)dst)[i] = ((const uint4*)sl)[i];
}

// =============================================================================
// SPARSE QKV conv (bit-exact vs dense skip-zero chain; ascending-c lists).
// Phase A: in-smem list build. Phase B: packed f32x2 accumulation
// (per-component rn == two scalar __fadd_rn; chain order unchanged).
// =============================================================================
#define SL_ 168

__global__ __launch_bounds__(512) void k_conv_sp3(const unsigned int* __restrict__ Mq,
                                                  const unsigned int* __restrict__ Mk,
                                                  const float* __restrict__ Wq,
                                                  const float* __restrict__ Wk,
                                                  const float* __restrict__ Wv,
                                                  float* __restrict__ Yq,
                                                  float* __restrict__ Yk,
                                                  float* __restrict__ Yv) {
    extern __shared__ float smem_sp[];
    float* ws = smem_sp;                             // [512 c][64 d] (128KB)
    float* otb = ws + 512 * 64;                      // 16 x [64][9] (36.9KB)
    unsigned short* slb = (unsigned short*)(otb + 16 * 576);  // 16 x 8 x SL_
    const int tid = threadIdx.x;
    const int lane = tid & 31, wid = tid >> 5;
    const int d0 = blockIdx.x * 64;
    const int z = blockIdx.z;
    const unsigned int* M = (z == 0) ? Mq : Mk;
    const float* W = (z == 0) ? Wq : (z == 1) ? Wk : Wv;
    float* Y = (z == 0) ? Yq : (z == 1) ? Yk : Yv;

    for (int i = tid; i < 8192; i += 512) {
        int dl = i >> 7;
        int c4 = (i & 127) << 2;
        float4 v = *(const float4*)&W[(size_t)(d0 + dl) * C_ + c4];
        ws[(c4 + 0) * 64 + dl] = v.x;
        ws[(c4 + 1) * 64 + dl] = v.y;
        ws[(c4 + 2) * 64 + dl] = v.z;
        ws[(c4 + 3) * 64 + dl] = v.w;
    }
    __syncthreads();

    float* ot = otb + wid * 576;
    unsigned short* sl = slb + wid * 8 * SL_;
    const int l2 = lane << 1;
    const int col = lane >> 2;
    const int seg = lane & 3;

    for (int tb = 0; tb < 4; tb++) {
        const int tbg = blockIdx.y * 4 + tb;
        const unsigned int* Mb = M + ((size_t)tbg << 14);
        float* Yb = Y + (size_t)tbg * CN_;

        for (int g = wid; g < 128; g += 16) {
            const int n0 = g * 8;

            // Phase A
            uint4 mm = *(const uint4*)(Mb + (size_t)(n0 + col) * 16 + seg * 4);
            int pc = __popc(mm.x) + __popc(mm.y) + __popc(mm.z) + __popc(mm.w);
            int s = pc, t;
            t = __shfl_up_sync(0xFFFFFFFFu, s, 1); if (seg >= 1) s += t;
            t = __shfl_up_sync(0xFFFFFFFFu, s, 2); if (seg >= 2) s += t;
            int pos = s - pc;
            {
                unsigned short* L = sl + col * SL_;
                unsigned int mw_[4] = {mm.x, mm.y, mm.z, mm.w};
#pragma unroll
                for (int w = 0; w < 4; w++) {
                    unsigned int m = mw_[w];
                    const int cb = seg * 128 + w * 32;
                    while (m) {
                        int j = __ffs((int)m) - 1;
                        m &= m - 1;
                        L[pos++] = (unsigned short)(cb + j);
                    }
                }
            }
            const int s_incl = s;
            __syncwarp();

            // Phase B (packed f32x2)
#pragma unroll
            for (int i8 = 0; i8 < 8; i8++) {
                const int cnt = __shfl_sync(0xFFFFFFFFu, s_incl, (i8 << 2) + 3);
                const unsigned short* L = sl + i8 * SL_;
                unsigned long long acc = 0ULL;
                int i = 0;
                for (; i + 4 <= cnt; i += 4) {
                    ushort4 c4 = *(const ushort4*)&L[i];
                    unsigned long long a0 = *(const unsigned long long*)&ws[((int)c4.x << 6) + l2];
                    unsigned long long a1 = *(const unsigned long long*)&ws[((int)c4.y << 6) + l2];
                    unsigned long long a2 = *(const unsigned long long*)&ws[((int)c4.z << 6) + l2];
                    unsigned long long a3 = *(const unsigned long long*)&ws[((int)c4.w << 6) + l2];
                    acc = add2(acc, a0);
                    acc = add2(acc, a1);
                    acc = add2(acc, a2);
                    acc = add2(acc, a3);
                }
                for (; i < cnt; i++) {
                    int c = L[i];
                    acc = add2(acc, *(const unsigned long long*)&ws[(c << 6) + l2]);
                }
                float ax, ay;
                asm("mov.b64 {%0, %1}, %2;" : "=f"(ax), "=f"(ay) : "l"(acc));
                ot[(l2 + 0) * 9 + i8] = ax;
                ot[(l2 + 1) * 9 + i8] = ay;
            }
            __syncwarp();
#pragma unroll
            for (int r = 0; r < 2; r++) {
                const int dl = lane + 32 * r;
                float4 v0 = make_float4(ot[dl * 9 + 0], ot[dl * 9 + 1],
                                        ot[dl * 9 + 2], ot[dl * 9 + 3]);
                float4 v1 = make_float4(ot[dl * 9 + 4], ot[dl * 9 + 5],
                                        ot[dl * 9 + 6], ot[dl * 9 + 7]);
                *(float4*)&Yb[(size_t)(d0 + dl) * N_ + n0] = v0;
                *(float4*)&Yb[(size_t)(d0 + dl) * N_ + n0 + 4] = v1;
            }
            __syncwarp();
        }
    }
}

// =============================================================================
// SPARSE proj conv from global lists (dense xs, ~45%): packed f32x2 chains,
// bias added after the chain (matches dense: acc-chain then +bias, rn).
// =============================================================================
__global__ __launch_bounds__(512) void k_conv_projL(const float* __restrict__ W,
                                                    const float* __restrict__ bias,
                                                    float* __restrict__ Y) {
    extern __shared__ float smem_pl[];
    float* ws = smem_pl;                 // [512][64] (128KB)
    float* otb = ws + 512 * 64;          // 16 x [64][9]
    const int tid = threadIdx.x;
    const int lane = tid & 31, wid = tid >> 5;
    const int d0 = blockIdx.x * 64;
    const int l2 = lane << 1;

    for (int i = tid; i < 8192; i += 512) {
        int dl = i >> 7;
        int c4 = (i & 127) << 2;
        float4 v = *(const float4*)&W[(size_t)(d0 + dl) * C_ + c4];
        ws[(c4 + 0) * 64 + dl] = v.x;
        ws[(c4 + 1) * 64 + dl] = v.y;
        ws[(c4 + 2) * 64 + dl] = v.z;
        ws[(c4 + 3) * 64 + dl] = v.w;
    }
    __syncthreads();

    unsigned long long bias2;
    {
        float bx = bias[d0 + l2], by = bias[d0 + l2 + 1];
        asm("mov.b64 %0, {%1, %2};" : "=l"(bias2) : "f"(bx), "f"(by));
    }

    float* ot = otb + wid * 576;

    for (int tb = 0; tb < 4; tb++) {
        const int tbg = blockIdx.y * 4 + tb;
        float* Yb = Y + (size_t)tbg * CN_;

        for (int g = wid; g < 128; g += 16) {
            const int n0 = g * 8;
#pragma unroll
            for (int i8 = 0; i8 < 8; i8++) {
                const int n = n0 + i8;
                const int cnt = g_cntx[tbg * N_ + n];
                const unsigned short* L = g_Lx + ((size_t)tbg * N_ + n) * 512;
                unsigned long long acc = 0ULL;
                int i = 0;
                for (; i + 4 <= cnt; i += 4) {
                    ushort4 c4 = *(const ushort4*)&L[i];
                    unsigned long long a0 = *(const unsigned long long*)&ws[((int)c4.x << 6) + l2];
                    unsigned long long a1 = *(const unsigned long long*)&ws[((int)c4.y << 6) + l2];
                    unsigned long long a2 = *(const unsigned long long*)&ws[((int)c4.z << 6) + l2];
                    unsigned long long a3 = *(const unsigned long long*)&ws[((int)c4.w << 6) + l2];
                    acc = add2(acc, a0);
                    acc = add2(acc, a1);
                    acc = add2(acc, a2);
                    acc = add2(acc, a3);
                }
                for (; i < cnt; i++) {
                    int c = L[i];
                    acc = add2(acc, *(const unsigned long long*)&ws[(c << 6) + l2]);
                }
                acc = add2(acc, bias2);
                float ax, ay;
                asm("mov.b64 {%0, %1}, %2;" : "=f"(ax), "=f"(ay) : "l"(acc));
                ot[(l2 + 0) * 9 + i8] = ax;
                ot[(l2 + 1) * 9 + i8] = ay;
            }
            __syncwarp();
#pragma unroll
            for (int r = 0; r < 2; r++) {
                const int dl = lane + 32 * r;
                float4 v0 = make_float4(ot[dl * 9 + 0], ot[dl * 9 + 1],
                                        ot[dl * 9 + 2], ot[dl * 9 + 3]);
                float4 v1 = make_float4(ot[dl * 9 + 4], ot[dl * 9 + 5],
                                        ot[dl * 9 + 6], ot[dl * 9 + 7]);
                *(float4*)&Yb[(size_t)(d0 + dl) * N_ + n0] = v0;
                *(float4*)&Yb[(size_t)(d0 + dl) * N_ + n0 + 4] = v1;
            }
            __syncwarp();
        }
    }
}

// =============================================================================
// BatchNorm stats emulating the XLA-GPU vectorized row-reduction bitwise.
// FROZEN — this schedule produced rel_err = 0.0.
// =============================================================================
__device__ __forceinline__ float block_tree_sum(float acc, float* warp_part,
                                                int tid) {
    int lane = tid & 31, wid = tid >> 5;
#pragma unroll
    for (int off = 16; off > 0; off >>= 1)
        acc = __fadd_rn(acc, __shfl_down_sync(0xFFFFFFFFu, acc, off));
    if (lane == 0) warp_part[wid] = acc;
    __syncthreads();
    float v = 0.0f;
    if (wid == 0) {
        v = (lane < 16) ? warp_part[lane] : 0.0f;
#pragma unroll
        for (int off = 16; off > 0; off >>= 1)
            v = __fadd_rn(v, __shfl_down_sync(0xFFFFFFFFu, v, off));
    }
    return v;
}

__global__ __launch_bounds__(512) void k_stats(const float* __restrict__ Yq,
                                               const float* __restrict__ Yk,
                                               const float* __restrict__ Yv,
                                               int idx_base) {
    __shared__ float warp_part[16];
    __shared__ float s_mean;
    const int idx = idx_base + blockIdx.y;
    const float* Y = (blockIdx.y == 0) ? Yq : (blockIdx.y == 1) ? Yk : Yv;
    const int c = blockIdx.x;
    const int tid = threadIdx.x;
    const float* Yc = Y + (size_t)c * N_ + 2 * tid;

    float ax = 0.0f, ay = 0.0f;
    for (int b = 0; b < TB_; b++) {
        float2 v = *(const float2*)(Yc + (size_t)b * CN_);
        ax = __fadd_rn(ax, v.x);
        ay = __fadd_rn(ay, v.y);
    }
    float total = block_tree_sum(__fadd_rn(ax, ay), warp_part, tid);
    if (tid == 0)
        s_mean = __fmul_rn(total, 1.52587890625e-05f);
    __syncthreads();
    const float m = s_mean;
    __syncthreads();

    ax = 0.0f; ay = 0.0f;
    for (int b = 0; b < TB_; b++) {
        float2 v = *(const float2*)(Yc + (size_t)b * CN_);
        float dx = __fsub_rn(v.x, m);
        ax = __fadd_rn(ax, __fmul_rn(dx, dx));
        float dy = __fsub_rn(v.y, m);
        ay = __fadd_rn(ay, __fmul_rn(dy, dy));
    }
    float tv = block_tree_sum(__fadd_rn(ax, ay), warp_part, tid);
    if (tid == 0) {
        float var = __fmul_rn(tv, 1.52587890625e-05f);
        g_mean[idx * C_ + c] = m;
        g_rstd[idx * C_ + c] = rsqrtf(__fadd_rn(var, 1e-5f));
    }
}

// =============================================================================
// v path: BN(yv) inline, LIF with carried-over membrane state -> vs2 spikes
// =============================================================================
__global__ __launch_bounds__(256) void k_vlif(const float* __restrict__ gam,
                                              const float* __restrict__ bet) {
    size_t i = (size_t)blockIdx.x * 256 + threadIdx.x;
    if (i >= BCN_) return;
    int c = (int)((i >> 10) & (C_ - 1));
    float m = g_mean[2 * C_ + c], r = g_rstd[2 * C_ + c];
    float ga = gam[c], be = bet[c];
    float v = g_vst[i];
#pragma unroll
    for (int t = 0; t < T_; t++) {
        size_t off = (size_t)t * BCN_ + i;
        float y = __fadd_rn(__fmul_rn(__fmul_rn(__fsub_rn(g_yv[off], m), r), ga), be);
        v = lif_up(v, y);
        unsigned char s = (v >= 1.0f) ? 1 : 0;
        g_vs2[off] = s;
        if (s) v = 0.0f;
    }
}

// =============================================================================
// Linear attention per (t,b,h). FROZEN sequential FFMA chains.
// =============================================================================
__global__ __launch_bounds__(256) void k_attn(const float* __restrict__ qg,
                                              const float* __restrict__ qbt,
                                              const float* __restrict__ kg,
                                              const float* __restrict__ kbt) {
    __shared__ float skv[64 * 68];
    __shared__ float sbuf[64 * 68];
    const int bx = blockIdx.x;
    const int t = bx >> 7, b = (bx >> 3) & 15, h = bx & 7;
    const size_t base = (size_t)(t * B_ + b) * CN_ + (size_t)(h * 64) * N_;
    const float* Yk = g_yk + base;
    const float* Yq = g_yq + base;
    const unsigned char* V = g_vs2 + base;
    float* X = g_x + base;
    const int tid = threadIdx.x;
    const int eg = (tid & 15) * 4;
    const int dg = (tid >> 4) * 4;

    float acc[4][4];
#pragma unroll
    for (int i = 0; i < 4; i++)
#pragma unroll
        for (int j = 0; j < 4; j++) acc[i][j] = 0.0f;

    float* sK = sbuf;
    float* sV = sbuf + 64 * 33;
    for (int n0 = 0; n0 < N_; n0 += 32) {
        __syncthreads();
        for (int idx = tid; idx < 2048; idx += 256) {
            int d = idx >> 5, n = idx & 31;
            int c = h * 64 + d;
            float mk = g_mean[C_ + c], rk = g_rstd[C_ + c];
            sK[d * 33 + n] = ((Yk[(size_t)d * N_ + n0 + n] - mk) * rk) * kg[c] + kbt[c];
            sV[d * 33 + n] = (float)V[(size_t)d * N_ + n0 + n];
        }
        __syncthreads();
#pragma unroll 8
        for (int n = 0; n < 32; n++) {
            float a0 = sK[(dg + 0) * 33 + n];
            float a1 = sK[(dg + 1) * 33 + n];
            float a2 = sK[(dg + 2) * 33 + n];
            float a3 = sK[(dg + 3) * 33 + n];
            float c0 = sV[(eg + 0) * 33 + n];
            float c1 = sV[(eg + 1) * 33 + n];
            float c2 = sV[(eg + 2) * 33 + n];
            float c3 = sV[(eg + 3) * 33 + n];
            acc[0][0] += a0 * c0; acc[0][1] += a0 * c1; acc[0][2] += a0 * c2; acc[0][3] += a0 * c3;
            acc[1][0] += a1 * c0; acc[1][1] += a1 * c1; acc[1][2] += a1 * c2; acc[1][3] += a1 * c3;
            acc[2][0] += a2 * c0; acc[2][1] += a2 * c1; acc[2][2] += a2 * c2; acc[2][3] += a2 * c3;
            acc[3][0] += a3 * c0; acc[3][1] += a3 * c1; acc[3][2] += a3 * c2; acc[3][3] += a3 * c3;
        }
    }
    __syncthreads();
#pragma unroll
    for (int i = 0; i < 4; i++)
#pragma unroll
        for (int j = 0; j < 4; j++) skv[(dg + i) * 68 + eg + j] = acc[i][j];
    __syncthreads();

    for (int n0 = 0; n0 < N_; n0 += 64) {
        for (int idx = tid; idx < 4096; idx += 256) {
            int d = idx >> 6, n = idx & 63;
            int c = h * 64 + d;
            float mq = g_mean[c], rq = g_rstd[c];
            sbuf[d * 68 + n] = ((Yq[(size_t)d * N_ + n0 + n] - mq) * rq) * qg[c] + qbt[c];
        }
        __syncthreads();
        float acc2[4][4];
#pragma unroll
        for (int i = 0; i < 4; i++)
#pragma unroll
            for (int j = 0; j < 4; j++) acc2[i][j] = 0.0f;
#pragma unroll 8
        for (int d = 0; d < 64; d++) {
            float4 qv = *(const float4*)&sbuf[d * 68 + eg];
            float k0v = skv[d * 68 + dg + 0];
            float k1v = skv[d * 68 + dg + 1];
            float k2v = skv[d * 68 + dg + 2];
            float k3v = skv[d * 68 + dg + 3];
            acc2[0][0] += k0v * qv.x; acc2[0][1] += k0v * qv.y; acc2[0][2] += k0v * qv.z; acc2[0][3] += k0v * qv.w;
            acc2[1][0] += k1v * qv.x; acc2[1][1] += k1v * qv.y; acc2[1][2] += k1v * qv.z; acc2[1][3] += k1v * qv.w;
            acc2[2][0] += k2v * qv.x; acc2[2][1] += k2v * qv.y; acc2[2][2] += k2v * qv.z; acc2[2][3] += k2v * qv.w;
            acc2[3][0] += k3v * qv.x; acc2[3][1] += k3v * qv.y; acc2[3][2] += k3v * qv.z; acc2[3][3] += k3v * qv.w;
        }
#pragma unroll
        for (int i = 0; i < 4; i++) {
            float4 o;
            o.x = acc2[i][0] * 0.125f;
            o.y = acc2[i][1] * 0.125f;
            o.z = acc2[i][2] * 0.125f;
            o.w = acc2[i][3] * 0.125f;
            *(float4*)&X[(size_t)(dg + i) * N_ + n0 + eg] = o;
        }
        __syncthreads();
    }
}

// =============================================================================
// attn_lif: thr = 0.5, fresh membrane
// =============================================================================
__global__ __launch_bounds__(256) void k_attnlif() {
    size_t i = (size_t)blockIdx.x * 256 + threadIdx.x;
    if (i >= BCN_) return;
    float v = 0.0f;
#pragma unroll
    for (int t = 0; t < T_; t++) {
        size_t off = (size_t)t * BCN_ + i;
        v = lif_up(v, g_x[off]);
        unsigned char s = (v >= 0.5f) ? 1 : 0;
        g_xs[off] = s;
        if (s) v = 0.0f;
    }
}

// =============================================================================
// final: BN(proj) inline, LIF thr=1.0, write float spikes to d_out
// =============================================================================
__global__ __launch_bounds__(256) void k_final(const float* __restrict__ gam,
                                               const float* __restrict__ bet,
                                               float* __restrict__ out) {
    size_t i = (size_t)blockIdx.x * 256 + threadIdx.x;
    if (i >= BCN_) return;
    int c = (int)((i >> 10) & (C_ - 1));
    float m = g_mean[3 * C_ + c], r = g_rstd[3 * C_ + c];
    float ga = gam[c], be = bet[c];
    float v = 0.0f;
#pragma unroll
    for (int t = 0; t < T_; t++) {
        size_t off = (size_t)t * BCN_ + i;
        float y = __fadd_rn(__fmul_rn(__fmul_rn(__fsub_rn(g_yv[off], m), r), ga), be);
        v = lif_up(v, y);
        unsigned char s = (v >= 1.0f) ? 1 : 0;
        out[off] = (float)s;
        if (s) v = 0.0f;
    }
}

// =============================================================================
// host
// =============================================================================
extern "C" void kernel_launch(void* const* d_in, const int* in_sizes, int n_in,
                              void* d_out, int out_size) {
    const float* q   = (const float*)d_in[0];
    const float* k   = (const float*)d_in[1];
    const float* Wq  = (const float*)d_in[2];
    const float* qg  = (const float*)d_in[3];
    const float* qb  = (const float*)d_in[4];
    const float* Wk  = (const float*)d_in[5];
    const float* kg  = (const float*)d_in[6];
    const float* kb  = (const float*)d_in[7];
    const float* Wv  = (const float*)d_in[8];
    const float* vg  = (const float*)d_in[9];
    const float* vb  = (const float*)d_in[10];
    const float* Wp  = (const float*)d_in[11];
    const float* Wpb = (const float*)d_in[12];
    const float* pg  = (const float*)d_in[13];
    const float* pb  = (const float*)d_in[14];
    float* out = (float*)d_out;

    void *p_yq, *p_yk, *p_yv, *p_Mq, *p_Mk;
    cudaGetSymbolAddress(&p_yq, g_yq);
    cudaGetSymbolAddress(&p_yk, g_yk);
    cudaGetSymbolAddress(&p_yv, g_yv);
    cudaGetSymbolAddress(&p_Mq, g_Mq);
    cudaGetSymbolAddress(&p_Mk, g_Mk);

    const int ew_blocks = (int)(BCN_ / 256);   // 32768
    dim3 gmask(N_ / 256, TB_);                 // (4, 64)
    dim3 gsp(8, 16, 3);                        // (dtile, tb-group, qkv)
    dim3 glists(N_ / 64, TB_);                 // (16, 64)
    dim3 gproj(8, 16);                         // (dtile, tb-group)
    dim3 gstats3(C_, 3);
    dim3 gstats1(C_, 1);

    const int SP_SMEM = 512 * 64 * 4 + 16 * 576 * 4 + 16 * 8 * SL_ * 2;  // 210944
    const int PL_SMEM = 512 * 64 * 4 + 16 * 576 * 4;                      // 167936
    const int LX_SMEM = 64 * 512 * 2;                                     // 65536
    cudaFuncSetAttribute(k_conv_sp3, cudaFuncAttributeMaxDynamicSharedMemorySize,
                         SP_SMEM);
    cudaFuncSetAttribute(k_conv_projL, cudaFuncAttributeMaxDynamicSharedMemorySize,
                         PL_SMEM);
    cudaFuncSetAttribute(k_lists_x, cudaFuncAttributeMaxDynamicSharedMemorySize,
                         LX_SMEM);

    k_lif_qk<<<ew_blocks, 256>>>(q, k);
    k_bitmask<<<gmask, 256>>>();
    k_conv_sp3<<<gsp, 512, SP_SMEM>>>((const unsigned int*)p_Mq,
                                      (const unsigned int*)p_Mk,
                                      Wq, Wk, Wv,
                                      (float*)p_yq, (float*)p_yk, (float*)p_yv);
    k_stats<<<gstats3, 512>>>((const float*)p_yq, (const float*)p_yk,
                              (const float*)p_yv, 0);
    k_vlif<<<ew_blocks, 256>>>(vg, vb);
    k_attn<<<T_ * B_ * H_, 256>>>(qg, qb, kg, kb);
    k_attnlif<<<ew_blocks, 256>>>();
    k_bitmask_x<<<gmask, 256>>>();
    k_lists_x<<<glists, 256, LX_SMEM>>>();
    k_conv_projL<<<gproj, 512, PL_SMEM>>>(Wp, Wpb, (float*)p_yv);
    k_stats<<<gstats1, 512>>>((const float*)p_yv, (const float*)p_yv,
                              (const float*)p_yv, 3);
    k_final<<<ew_blocks, 256>>>(pg, pb, out);
}

// round 16
// speedup vs baseline: 1.4487x; 1.4487x over previous
#include <cuda_runtime.h>
#include <cuda_bf16.h>

#define T_ 4
#define B_ 16
#define C_ 512
#define N_ 1024
#define H_ 8
#define TB_ (T_ * B_)
#define CN_ (C_ * N_)                      // 524288
#define BCN_ ((size_t)B_ * CN_)            // 8388608
#define TBCN_ ((size_t)T_ * B_ * CN_)      // 33554432

// ---------------- scratch (device globals; allocations forbidden) -----------
__device__ float g_yq[TBCN_];
__device__ float g_yk[TBCN_];
__device__ float g_yv[TBCN_];   // reused for proj conv output
__device__ float g_x[TBCN_];
__device__ unsigned char g_qs[TBCN_];
__device__ unsigned char g_ks[TBCN_];
__device__ unsigned char g_vs2[TBCN_];
__device__ unsigned char g_xs[TBCN_];
__device__ float g_vst[BCN_];
__device__ float g_mean[4 * C_];
__device__ float g_rstd[4 * C_];
__device__ unsigned int g_Mq[(size_t)TB_ * N_ * 16];   // column bitmasks, 4MB
__device__ unsigned int g_Mk[(size_t)TB_ * N_ * 16];

// LIF membrane update: rn(v + rn(x - v)/2) — bit-exact vs reference.
__device__ __forceinline__ float lif_up(float v, float x) {
    return __fmaf_rn(__fsub_rn(x, v), 0.5f, v);
}

// Packed f32x2 add, per-component round-to-nearest == two scalar __fadd_rn.
__device__ __forceinline__ unsigned long long add2(unsigned long long a,
                                                   unsigned long long b) {
    unsigned long long r;
    asm("add.rn.f32x2 %0, %1, %2;" : "=l"(r) : "l"(a), "l"(b));
    return r;
}

// =============================================================================
// LIF over q and k simultaneously (vs == ks in the reference; keep k membrane)
// =============================================================================
__global__ __launch_bounds__(256) void k_lif_qk(const float* __restrict__ q,
                                                const float* __restrict__ k) {
    size_t i = (size_t)blockIdx.x * 256 + threadIdx.x;
    if (i >= BCN_) return;
    float vq = 0.0f, vk = 0.0f;
#pragma unroll
    for (int t = 0; t < T_; t++) {
        size_t off = (size_t)t * BCN_ + i;
        vq = lif_up(vq, q[off]);
        unsigned char s = (vq >= 1.0f) ? 1 : 0;
        g_qs[off] = s;
        if (s) vq = 0.0f;
        vk = lif_up(vk, k[off]);
        s = (vk >= 1.0f) ? 1 : 0;
        g_ks[off] = s;
        if (s) vk = 0.0f;
    }
    g_vst[i] = vk;
}

// =============================================================================
// Build per-column channel bitmasks for qs and ks spikes.
// =============================================================================
__global__ __launch_bounds__(256) void k_bitmask() {
    const int tb = blockIdx.y;
    const int n = blockIdx.x * 256 + threadIdx.x;
    const unsigned char* Sq = g_qs + (size_t)tb * CN_ + n;
    const unsigned char* Sk = g_ks + (size_t)tb * CN_ + n;
    unsigned int* Mq = g_Mq + ((size_t)tb * N_ + n) * 16;
    unsigned int* Mk = g_Mk + ((size_t)tb * N_ + n) * 16;
#pragma unroll
    for (int w = 0; w < 16; w++) {
        unsigned int mq = 0, mk = 0;
#pragma unroll
        for (int j = 0; j < 32; j++) {
            int c = w * 32 + j;
            mq |= ((unsigned int)Sq[(size_t)c * N_]) << j;
            mk |= ((unsigned int)Sk[(size_t)c * N_]) << j;
        }
        Mq[w] = mq;
        Mk[w] = mk;
    }
}

// =============================================================================
// SPARSE QKV conv (bit-exact vs dense skip-zero chain; ascending-c lists).
// Phase A: in-smem list build. Phase B: counted loop unroll x4, packed f32x2
// accumulation (per-component rn == two scalar __fadd_rn; order unchanged).
// =============================================================================
#define SL_ 168

__global__ __launch_bounds__(512) void k_conv_sp3(const unsigned int* __restrict__ Mq,
                                                  const unsigned int* __restrict__ Mk,
                                                  const float* __restrict__ Wq,
                                                  const float* __restrict__ Wk,
                                                  const float* __restrict__ Wv,
                                                  float* __restrict__ Yq,
                                                  float* __restrict__ Yk,
                                                  float* __restrict__ Yv) {
    extern __shared__ float smem_sp[];
    float* ws = smem_sp;                             // [512 c][64 d] (128KB)
    float* otb = ws + 512 * 64;                      // 16 x [64][9] (36.9KB)
    unsigned short* slb = (unsigned short*)(otb + 16 * 576);  // 16 x 8 x SL_
    const int tid = threadIdx.x;
    const int lane = tid & 31, wid = tid >> 5;
    const int d0 = blockIdx.x * 64;
    const int z = blockIdx.z;
    const unsigned int* M = (z == 0) ? Mq : Mk;
    const float* W = (z == 0) ? Wq : (z == 1) ? Wk : Wv;
    float* Y = (z == 0) ? Yq : (z == 1) ? Yk : Yv;

    for (int i = tid; i < 8192; i += 512) {
        int dl = i >> 7;
        int c4 = (i & 127) << 2;
        float4 v = *(const float4*)&W[(size_t)(d0 + dl) * C_ + c4];
        ws[(c4 + 0) * 64 + dl] = v.x;
        ws[(c4 + 1) * 64 + dl] = v.y;
        ws[(c4 + 2) * 64 + dl] = v.z;
        ws[(c4 + 3) * 64 + dl] = v.w;
    }
    __syncthreads();

    float* ot = otb + wid * 576;
    unsigned short* sl = slb + wid * 8 * SL_;
    const int l2 = lane << 1;
    const int col = lane >> 2;
    const int seg = lane & 3;

    for (int tb = 0; tb < 4; tb++) {
        const int tbg = blockIdx.y * 4 + tb;
        const unsigned int* Mb = M + ((size_t)tbg << 14);
        float* Yb = Y + (size_t)tbg * CN_;

        for (int g = wid; g < 128; g += 16) {
            const int n0 = g * 8;

            // Phase A: build ascending index lists for 8 columns
            uint4 mm = *(const uint4*)(Mb + (size_t)(n0 + col) * 16 + seg * 4);
            int pc = __popc(mm.x) + __popc(mm.y) + __popc(mm.z) + __popc(mm.w);
            int s = pc, t;
            t = __shfl_up_sync(0xFFFFFFFFu, s, 1); if (seg >= 1) s += t;
            t = __shfl_up_sync(0xFFFFFFFFu, s, 2); if (seg >= 2) s += t;
            int pos = s - pc;
            {
                unsigned short* L = sl + col * SL_;
                unsigned int mw_[4] = {mm.x, mm.y, mm.z, mm.w};
#pragma unroll
                for (int w = 0; w < 4; w++) {
                    unsigned int m = mw_[w];
                    const int cb = seg * 128 + w * 32;
                    while (m) {
                        int j = __ffs((int)m) - 1;
                        m &= m - 1;
                        L[pos++] = (unsigned short)(cb + j);
                    }
                }
            }
            const int s_incl = s;
            __syncwarp();

            // Phase B: packed f32x2 accumulation, ascending c
#pragma unroll
            for (int i8 = 0; i8 < 8; i8++) {
                const int cnt = __shfl_sync(0xFFFFFFFFu, s_incl, (i8 << 2) + 3);
                const unsigned short* L = sl + i8 * SL_;
                unsigned long long acc = 0ULL;
                int i = 0;
                for (; i + 4 <= cnt; i += 4) {
                    ushort4 c4 = *(const ushort4*)&L[i];
                    unsigned long long a0 = *(const unsigned long long*)&ws[((int)c4.x << 6) + l2];
                    unsigned long long a1 = *(const unsigned long long*)&ws[((int)c4.y << 6) + l2];
                    unsigned long long a2 = *(const unsigned long long*)&ws[((int)c4.z << 6) + l2];
                    unsigned long long a3 = *(const unsigned long long*)&ws[((int)c4.w << 6) + l2];
                    acc = add2(acc, a0);
                    acc = add2(acc, a1);
                    acc = add2(acc, a2);
                    acc = add2(acc, a3);
                }
                for (; i < cnt; i++) {
                    int c = L[i];
                    acc = add2(acc, *(const unsigned long long*)&ws[(c << 6) + l2]);
                }
                float ax, ay;
                asm("mov.b64 {%0, %1}, %2;" : "=f"(ax), "=f"(ay) : "l"(acc));
                ot[(l2 + 0) * 9 + i8] = ax;
                ot[(l2 + 1) * 9 + i8] = ay;
            }
            __syncwarp();
#pragma unroll
            for (int r = 0; r < 2; r++) {
                const int dl = lane + 32 * r;
                float4 v0 = make_float4(ot[dl * 9 + 0], ot[dl * 9 + 1],
                                        ot[dl * 9 + 2], ot[dl * 9 + 3]);
                float4 v1 = make_float4(ot[dl * 9 + 4], ot[dl * 9 + 5],
                                        ot[dl * 9 + 6], ot[dl * 9 + 7]);
                *(float4*)&Yb[(size_t)(d0 + dl) * N_ + n0] = v0;
                *(float4*)&Yb[(size_t)(d0 + dl) * N_ + n0 + 4] = v1;
            }
            __syncwarp();
        }
    }
}

// =============================================================================
// Dense conv (1x1 == GEMM), fp32 single ascending-c FFMA chain per output.
// FROZEN numerics. Used for the proj conv (xs is ~45% dense — sparse loses).
// =============================================================================
__global__ __launch_bounds__(256) void k_conv(const unsigned char* __restrict__ S,
                                              const float* __restrict__ W,
                                              const float* __restrict__ bias,
                                              float* __restrict__ Y) {
    __shared__ float sW[8][132];
    __shared__ float sS[8][132];
    const int tid = threadIdx.x;
    const int n0 = blockIdx.x * 128;
    const int d0 = blockIdx.y * 128;
    const size_t base = (size_t)blockIdx.z * CN_;
    const unsigned char* Sb = S + base;
    float* Yb = Y + base;

    const int tx4 = (tid & 15) * 4;
    const int ty4 = (tid >> 4) * 4;

    const int wrow = tid >> 1;
    const int wcol = (tid & 1) * 4;
    const int srow = tid >> 5;
    const int scol = (tid & 31) * 4;

    float acc[8][8];
#pragma unroll
    for (int i = 0; i < 8; i++)
#pragma unroll
        for (int j = 0; j < 8; j++) acc[i][j] = 0.0f;

    for (int k0 = 0; k0 < C_; k0 += 8) {
        float4 wv = *(const float4*)&W[(size_t)(d0 + wrow) * C_ + k0 + wcol];
        uchar4 sv = *(const uchar4*)&Sb[(size_t)(k0 + srow) * N_ + n0 + scol];
        __syncthreads();
        sW[wcol + 0][wrow] = wv.x;
        sW[wcol + 1][wrow] = wv.y;
        sW[wcol + 2][wrow] = wv.z;
        sW[wcol + 3][wrow] = wv.w;
        sS[srow][scol + 0] = (float)sv.x;
        sS[srow][scol + 1] = (float)sv.y;
        sS[srow][scol + 2] = (float)sv.z;
        sS[srow][scol + 3] = (float)sv.w;
        __syncthreads();
#pragma unroll
        for (int kk = 0; kk < 8; kk++) {
            float4 a0 = *(const float4*)&sW[kk][ty4];
            float4 a1 = *(const float4*)&sW[kk][ty4 + 64];
            float4 b0 = *(const float4*)&sS[kk][tx4];
            float4 b1 = *(const float4*)&sS[kk][tx4 + 64];
            float a[8] = {a0.x, a0.y, a0.z, a0.w, a1.x, a1.y, a1.z, a1.w};
            float b[8] = {b0.x, b0.y, b0.z, b0.w, b1.x, b1.y, b1.z, b1.w};
#pragma unroll
            for (int i = 0; i < 8; i++)
#pragma unroll
                for (int j = 0; j < 8; j++) acc[i][j] += a[i] * b[j];
        }
    }

#pragma unroll
    for (int qi = 0; qi < 2; qi++)
#pragma unroll
        for (int i = 0; i < 4; i++) {
            int d = d0 + qi * 64 + ty4 + i;
            float bs = bias ? bias[d] : 0.0f;
#pragma unroll
            for (int qj = 0; qj < 2; qj++) {
                float4 o;
                o.x = acc[qi * 4 + i][qj * 4 + 0] + bs;
                o.y = acc[qi * 4 + i][qj * 4 + 1] + bs;
                o.z = acc[qi * 4 + i][qj * 4 + 2] + bs;
                o.w = acc[qi * 4 + i][qj * 4 + 3] + bs;
                *(float4*)&Yb[(size_t)d * N_ + n0 + qj * 64 + tx4] = o;
            }
        }
}

// =============================================================================
// BatchNorm stats emulating the XLA-GPU vectorized row-reduction bitwise.
// FROZEN — this schedule produced rel_err = 0.0.
// =============================================================================
__device__ __forceinline__ float block_tree_sum(float acc, float* warp_part,
                                                int tid) {
    int lane = tid & 31, wid = tid >> 5;
#pragma unroll
    for (int off = 16; off > 0; off >>= 1)
        acc = __fadd_rn(acc, __shfl_down_sync(0xFFFFFFFFu, acc, off));
    if (lane == 0) warp_part[wid] = acc;
    __syncthreads();
    float v = 0.0f;
    if (wid == 0) {
        v = (lane < 16) ? warp_part[lane] : 0.0f;
#pragma unroll
        for (int off = 16; off > 0; off >>= 1)
            v = __fadd_rn(v, __shfl_down_sync(0xFFFFFFFFu, v, off));
    }
    return v;
}

__global__ __launch_bounds__(512) void k_stats(const float* __restrict__ Yq,
                                               const float* __restrict__ Yk,
                                               const float* __restrict__ Yv,
                                               int idx_base) {
    __shared__ float warp_part[16];
    __shared__ float s_mean;
    const int idx = idx_base + blockIdx.y;
    const float* Y = (blockIdx.y == 0) ? Yq : (blockIdx.y == 1) ? Yk : Yv;
    const int c = blockIdx.x;
    const int tid = threadIdx.x;
    const float* Yc = Y + (size_t)c * N_ + 2 * tid;

    float ax = 0.0f, ay = 0.0f;
    for (int b = 0; b < TB_; b++) {
        float2 v = *(const float2*)(Yc + (size_t)b * CN_);
        ax = __fadd_rn(ax, v.x);
        ay = __fadd_rn(ay, v.y);
    }
    float total = block_tree_sum(__fadd_rn(ax, ay), warp_part, tid);
    if (tid == 0)
        s_mean = __fmul_rn(total, 1.52587890625e-05f);
    __syncthreads();
    const float m = s_mean;
    __syncthreads();

    ax = 0.0f; ay = 0.0f;
    for (int b = 0; b < TB_; b++) {
        float2 v = *(const float2*)(Yc + (size_t)b * CN_);
        float dx = __fsub_rn(v.x, m);
        ax = __fadd_rn(ax, __fmul_rn(dx, dx));
        float dy = __fsub_rn(v.y, m);
        ay = __fadd_rn(ay, __fmul_rn(dy, dy));
    }
    float tv = block_tree_sum(__fadd_rn(ax, ay), warp_part, tid);
    if (tid == 0) {
        float var = __fmul_rn(tv, 1.52587890625e-05f);
        g_mean[idx * C_ + c] = m;
        g_rstd[idx * C_ + c] = rsqrtf(__fadd_rn(var, 1e-5f));
    }
}

// =============================================================================
// v path: BN(yv) inline, LIF with carried-over membrane state -> vs2 spikes
// =============================================================================
__global__ __launch_bounds__(256) void k_vlif(const float* __restrict__ gam,
                                              const float* __restrict__ bet) {
    size_t i = (size_t)blockIdx.x * 256 + threadIdx.x;
    if (i >= BCN_) return;
    int c = (int)((i >> 10) & (C_ - 1));
    float m = g_mean[2 * C_ + c], r = g_rstd[2 * C_ + c];
    float ga = gam[c], be = bet[c];
    float v = g_vst[i];
#pragma unroll
    for (int t = 0; t < T_; t++) {
        size_t off = (size_t)t * BCN_ + i;
        float y = __fadd_rn(__fmul_rn(__fmul_rn(__fsub_rn(g_yv[off], m), r), ga), be);
        v = lif_up(v, y);
        unsigned char s = (v >= 1.0f) ? 1 : 0;
        g_vs2[off] = s;
        if (s) v = 0.0f;
    }
}

// =============================================================================
// Linear attention per (t,b,h). FROZEN sequential FFMA chains.
// =============================================================================
__global__ __launch_bounds__(256) void k_attn(const float* __restrict__ qg,
                                              const float* __restrict__ qbt,
                                              const float* __restrict__ kg,
                                              const float* __restrict__ kbt) {
    __shared__ float skv[64 * 68];
    __shared__ float sbuf[64 * 68];
    const int bx = blockIdx.x;
    const int t = bx >> 7, b = (bx >> 3) & 15, h = bx & 7;
    const size_t base = (size_t)(t * B_ + b) * CN_ + (size_t)(h * 64) * N_;
    const float* Yk = g_yk + base;
    const float* Yq = g_yq + base;
    const unsigned char* V = g_vs2 + base;
    float* X = g_x + base;
    const int tid = threadIdx.x;
    const int eg = (tid & 15) * 4;
    const int dg = (tid >> 4) * 4;

    float acc[4][4];
#pragma unroll
    for (int i = 0; i < 4; i++)
#pragma unroll
        for (int j = 0; j < 4; j++) acc[i][j] = 0.0f;

    float* sK = sbuf;
    float* sV = sbuf + 64 * 33;
    for (int n0 = 0; n0 < N_; n0 += 32) {
        __syncthreads();
        for (int idx = tid; idx < 2048; idx += 256) {
            int d = idx >> 5, n = idx & 31;
            int c = h * 64 + d;
            float mk = g_mean[C_ + c], rk = g_rstd[C_ + c];
            sK[d * 33 + n] = ((Yk[(size_t)d * N_ + n0 + n] - mk) * rk) * kg[c] + kbt[c];
            sV[d * 33 + n] = (float)V[(size_t)d * N_ + n0 + n];
        }
        __syncthreads();
#pragma unroll 8
        for (int n = 0; n < 32; n++) {
            float a0 = sK[(dg + 0) * 33 + n];
            float a1 = sK[(dg + 1) * 33 + n];
            float a2 = sK[(dg + 2) * 33 + n];
            float a3 = sK[(dg + 3) * 33 + n];
            float c0 = sV[(eg + 0) * 33 + n];
            float c1 = sV[(eg + 1) * 33 + n];
            float c2 = sV[(eg + 2) * 33 + n];
            float c3 = sV[(eg + 3) * 33 + n];
            acc[0][0] += a0 * c0; acc[0][1] += a0 * c1; acc[0][2] += a0 * c2; acc[0][3] += a0 * c3;
            acc[1][0] += a1 * c0; acc[1][1] += a1 * c1; acc[1][2] += a1 * c2; acc[1][3] += a1 * c3;
            acc[2][0] += a2 * c0; acc[2][1] += a2 * c1; acc[2][2] += a2 * c2; acc[2][3] += a2 * c3;
            acc[3][0] += a3 * c0; acc[3][1] += a3 * c1; acc[3][2] += a3 * c2; acc[3][3] += a3 * c3;
        }
    }
    __syncthreads();
#pragma unroll
    for (int i = 0; i < 4; i++)
#pragma unroll
        for (int j = 0; j < 4; j++) skv[(dg + i) * 68 + eg + j] = acc[i][j];
    __syncthreads();

    for (int n0 = 0; n0 < N_; n0 += 64) {
        for (int idx = tid; idx < 4096; idx += 256) {
            int d = idx >> 6, n = idx & 63;
            int c = h * 64 + d;
            float mq = g_mean[c], rq = g_rstd[c];
            sbuf[d * 68 + n] = ((Yq[(size_t)d * N_ + n0 + n] - mq) * rq) * qg[c] + qbt[c];
        }
        __syncthreads();
        float acc2[4][4];
#pragma unroll
        for (int i = 0; i < 4; i++)
#pragma unroll
            for (int j = 0; j < 4; j++) acc2[i][j] = 0.0f;
#pragma unroll 8
        for (int d = 0; d < 64; d++) {
            float4 qv = *(const float4*)&sbuf[d * 68 + eg];
            float k0v = skv[d * 68 + dg + 0];
            float k1v = skv[d * 68 + dg + 1];
            float k2v = skv[d * 68 + dg + 2];
            float k3v = skv[d * 68 + dg + 3];
            acc2[0][0] += k0v * qv.x; acc2[0][1] += k0v * qv.y; acc2[0][2] += k0v * qv.z; acc2[0][3] += k0v * qv.w;
            acc2[1][0] += k1v * qv.x; acc2[1][1] += k1v * qv.y; acc2[1][2] += k1v * qv.z; acc2[1][3] += k1v * qv.w;
            acc2[2][0] += k2v * qv.x; acc2[2][1] += k2v * qv.y; acc2[2][2] += k2v * qv.z; acc2[2][3] += k2v * qv.w;
            acc2[3][0] += k3v * qv.x; acc2[3][1] += k3v * qv.y; acc2[3][2] += k3v * qv.z; acc2[3][3] += k3v * qv.w;
        }
#pragma unroll
        for (int i = 0; i < 4; i++) {
            float4 o;
            o.x = acc2[i][0] * 0.125f;
            o.y = acc2[i][1] * 0.125f;
            o.z = acc2[i][2] * 0.125f;
            o.w = acc2[i][3] * 0.125f;
            *(float4*)&X[(size_t)(dg + i) * N_ + n0 + eg] = o;
        }
        __syncthreads();
    }
}

// =============================================================================
// attn_lif: thr = 0.5, fresh membrane
// =============================================================================
__global__ __launch_bounds__(256) void k_attnlif() {
    size_t i = (size_t)blockIdx.x * 256 + threadIdx.x;
    if (i >= BCN_) return;
    float v = 0.0f;
#pragma unroll
    for (int t = 0; t < T_; t++) {
        size_t off = (size_t)t * BCN_ + i;
        v = lif_up(v, g_x[off]);
        unsigned char s = (v >= 0.5f) ? 1 : 0;
        g_xs[off] = s;
        if (s) v = 0.0f;
    }
}

// =============================================================================
// final: BN(proj) inline, LIF thr=1.0, write float spikes to d_out
// =============================================================================
__global__ __launch_bounds__(256) void k_final(const float* __restrict__ gam,
                                               const float* __restrict__ bet,
                                               float* __restrict__ out) {
    size_t i = (size_t)blockIdx.x * 256 + threadIdx.x;
    if (i >= BCN_) return;
    int c = (int)((i >> 10) & (C_ - 1));
    float m = g_mean[3 * C_ + c], r = g_rstd[3 * C_ + c];
    float ga = gam[c], be = bet[c];
    float v = 0.0f;
#pragma unroll
    for (int t = 0; t < T_; t++) {
        size_t off = (size_t)t * BCN_ + i;
        float y = __fadd_rn(__fmul_rn(__fmul_rn(__fsub_rn(g_yv[off], m), r), ga), be);
        v = lif_up(v, y);
        unsigned char s = (v >= 1.0f) ? 1 : 0;
        out[off] = (float)s;
        if (s) v = 0.0f;
    }
}

// =============================================================================
// host
// =============================================================================
extern "C" void kernel_launch(void* const* d_in, const int* in_sizes, int n_in,
                              void* d_out, int out_size) {
    const float* q   = (const float*)d_in[0];
    const float* k   = (const float*)d_in[1];
    const float* Wq  = (const float*)d_in[2];
    const float* qg  = (const float*)d_in[3];
    const float* qb  = (const float*)d_in[4];
    const float* Wk  = (const float*)d_in[5];
    const float* kg  = (const float*)d_in[6];
    const float* kb  = (const float*)d_in[7];
    const float* Wv  = (const float*)d_in[8];
    const float* vg  = (const float*)d_in[9];
    const float* vb  = (const float*)d_in[10];
    const float* Wp  = (const float*)d_in[11];
    const float* Wpb = (const float*)d_in[12];
    const float* pg  = (const float*)d_in[13];
    const float* pb  = (const float*)d_in[14];
    float* out = (float*)d_out;

    void *p_xs, *p_yq, *p_yk, *p_yv, *p_Mq, *p_Mk;
    cudaGetSymbolAddress(&p_xs, g_xs);
    cudaGetSymbolAddress(&p_yq, g_yq);
    cudaGetSymbolAddress(&p_yk, g_yk);
    cudaGetSymbolAddress(&p_yv, g_yv);
    cudaGetSymbolAddress(&p_Mq, g_Mq);
    cudaGetSymbolAddress(&p_Mk, g_Mk);

    const int ew_blocks = (int)(BCN_ / 256);   // 32768
    dim3 gconv(N_ / 128, C_ / 128, TB_);       // dense proj conv
    dim3 gmask(N_ / 256, TB_);                 // (4, 64)
    dim3 gsp(8, 16, 3);                        // (dtile, tb-group, qkv)
    dim3 gstats3(C_, 3);
    dim3 gstats1(C_, 1);

    const int SP_SMEM = 512 * 64 * 4 + 16 * 576 * 4 + 16 * 8 * SL_ * 2;  // 210944
    cudaFuncSetAttribute(k_conv_sp3, cudaFuncAttributeMaxDynamicSharedMemorySize,
                         SP_SMEM);

    k_lif_qk<<<ew_blocks, 256>>>(q, k);
    k_bitmask<<<gmask, 256>>>();
    k_conv_sp3<<<gsp, 512, SP_SMEM>>>((const unsigned int*)p_Mq,
                                      (const unsigned int*)p_Mk,
                                      Wq, Wk, Wv,
                                      (float*)p_yq, (float*)p_yk, (float*)p_yv);
    k_stats<<<gstats3, 512>>>((const float*)p_yq, (const float*)p_yk,
                              (const float*)p_yv, 0);
    k_vlif<<<ew_blocks, 256>>>(vg, vb);
    k_attn<<<T_ * B_ * H_, 256>>>(qg, qb, kg, kb);
    k_attnlif<<<ew_blocks, 256>>>();
    k_conv<<<gconv, 256>>>((const unsigned char*)p_xs, Wp, Wpb, (float*)p_yv);
    k_stats<<<gstats1, 512>>>((const float*)p_yv, (const float*)p_yv,
                              (const float*)p_yv, 3);
    k_final<<<ew_blocks, 256>>>(pg, pb, out);
}

// round 17
// speedup vs baseline: 1.4894x; 1.0281x over previous
#include <cuda_runtime.h>
#include <cuda_bf16.h>

#define T_ 4
#define B_ 16
#define C_ 512
#define N_ 1024
#define H_ 8
#define TB_ (T_ * B_)
#define CN_ (C_ * N_)                      // 524288
#define BCN_ ((size_t)B_ * CN_)            // 8388608
#define TBCN_ ((size_t)T_ * B_ * CN_)      // 33554432

// ---------------- scratch (device globals; allocations forbidden) -----------
__device__ float g_yq[TBCN_];
__device__ float g_yk[TBCN_];
__device__ float g_yv[TBCN_];   // reused for proj conv output
__device__ unsigned char g_qs[TBCN_];
__device__ unsigned char g_ks[TBCN_];
__device__ unsigned char g_vs2[TBCN_];
__device__ unsigned char g_xs[TBCN_];
__device__ float g_vst[BCN_];
__device__ float g_mean[4 * C_];
__device__ float g_rstd[4 * C_];
__device__ unsigned int g_Mq[(size_t)TB_ * N_ * 16];   // column bitmasks, 4MB
__device__ unsigned int g_Mk[(size_t)TB_ * N_ * 16];

// LIF membrane update: rn(v + rn(x - v)/2) — bit-exact vs reference.
__device__ __forceinline__ float lif_up(float v, float x) {
    return __fmaf_rn(__fsub_rn(x, v), 0.5f, v);
}

// Packed f32x2 add, per-component round-to-nearest == two scalar __fadd_rn.
__device__ __forceinline__ unsigned long long add2(unsigned long long a,
                                                   unsigned long long b) {
    unsigned long long r;
    asm("add.rn.f32x2 %0, %1, %2;" : "=l"(r) : "l"(a), "l"(b));
    return r;
}

// =============================================================================
// LIF over q and k simultaneously (vs == ks in the reference; keep k membrane)
// =============================================================================
__global__ __launch_bounds__(256) void k_lif_qk(const float* __restrict__ q,
                                                const float* __restrict__ k) {
    size_t i = (size_t)blockIdx.x * 256 + threadIdx.x;
    if (i >= BCN_) return;
    float vq = 0.0f, vk = 0.0f;
#pragma unroll
    for (int t = 0; t < T_; t++) {
        size_t off = (size_t)t * BCN_ + i;
        vq = lif_up(vq, q[off]);
        unsigned char s = (vq >= 1.0f) ? 1 : 0;
        g_qs[off] = s;
        if (s) vq = 0.0f;
        vk = lif_up(vk, k[off]);
        s = (vk >= 1.0f) ? 1 : 0;
        g_ks[off] = s;
        if (s) vk = 0.0f;
    }
    g_vst[i] = vk;
}

// =============================================================================
// Build per-column channel bitmasks for qs and ks spikes.
// =============================================================================
__global__ __launch_bounds__(256) void k_bitmask() {
    const int tb = blockIdx.y;
    const int n = blockIdx.x * 256 + threadIdx.x;
    const unsigned char* Sq = g_qs + (size_t)tb * CN_ + n;
    const unsigned char* Sk = g_ks + (size_t)tb * CN_ + n;
    unsigned int* Mq = g_Mq + ((size_t)tb * N_ + n) * 16;
    unsigned int* Mk = g_Mk + ((size_t)tb * N_ + n) * 16;
#pragma unroll
    for (int w = 0; w < 16; w++) {
        unsigned int mq = 0, mk = 0;
#pragma unroll
        for (int j = 0; j < 32; j++) {
            int c = w * 32 + j;
            mq |= ((unsigned int)Sq[(size_t)c * N_]) << j;
            mk |= ((unsigned int)Sk[(size_t)c * N_]) << j;
        }
        Mq[w] = mq;
        Mk[w] = mk;
    }
}

// =============================================================================
// SPARSE QKV conv, bit-exact vs the dense skip-zero chain.
// Phase A: build ascending index lists, TRANSPOSED (slT[i*8+col]) and padded
//   to the 8-column max with index 512 -> zero weight row (+0.0 add is an
//   identity: acc is never -0).
// Phase B: uniform counted loop, 8 independent add2 chains (ILP 8); each
//   column's chain remains strictly ascending c -> bit-exact.
// =============================================================================
#define SL_ 168

__global__ __launch_bounds__(512) void k_conv_sp3(const unsigned int* __restrict__ Mq,
                                                  const unsigned int* __restrict__ Mk,
                                                  const float* __restrict__ Wq,
                                                  const float* __restrict__ Wk,
                                                  const float* __restrict__ Wv,
                                                  float* __restrict__ Yq,
                                                  float* __restrict__ Yk,
                                                  float* __restrict__ Yv) {
    extern __shared__ float smem_sp[];
    float* ws = smem_sp;                              // [513 c][64 d] (131.3KB)
    float* otb = ws + 513 * 64;                       // 16 x [64][9] (36.9KB)
    unsigned short* slb = (unsigned short*)(otb + 16 * 576);  // 16 x [SL_][8]
    const int tid = threadIdx.x;
    const int lane = tid & 31, wid = tid >> 5;
    const int d0 = blockIdx.x * 64;
    const int z = blockIdx.z;
    const unsigned int* M = (z == 0) ? Mq : Mk;
    const float* W = (z == 0) ? Wq : (z == 1) ? Wk : Wv;
    float* Y = (z == 0) ? Yq : (z == 1) ? Yk : Yv;

    for (int i = tid; i < 8192; i += 512) {
        int dl = i >> 7;
        int c4 = (i & 127) << 2;
        float4 v = *(const float4*)&W[(size_t)(d0 + dl) * C_ + c4];
        ws[(c4 + 0) * 64 + dl] = v.x;
        ws[(c4 + 1) * 64 + dl] = v.y;
        ws[(c4 + 2) * 64 + dl] = v.z;
        ws[(c4 + 3) * 64 + dl] = v.w;
    }
    if (tid < 16) {      // zero pad row c=512
        float4 zz = make_float4(0.f, 0.f, 0.f, 0.f);
        *(float4*)&ws[512 * 64 + tid * 4] = zz;
    }
    __syncthreads();

    float* ot = otb + wid * 576;
    unsigned short* slT = slb + wid * (SL_ * 8);
    const int l2 = lane << 1;
    const int col = lane >> 2;
    const int seg = lane & 3;

    for (int tb = 0; tb < 4; tb++) {
        const int tbg = blockIdx.y * 4 + tb;
        const unsigned int* Mb = M + ((size_t)tbg << 14);
        float* Yb = Y + (size_t)tbg * CN_;

        for (int g = wid; g < 128; g += 16) {
            const int n0 = g * 8;

            // ---- Phase A: transposed ascending lists + padding ----
            uint4 mm = *(const uint4*)(Mb + (size_t)(n0 + col) * 16 + seg * 4);
            int pc = __popc(mm.x) + __popc(mm.y) + __popc(mm.z) + __popc(mm.w);
            int s = pc, t;
            t = __shfl_up_sync(0xFFFFFFFFu, s, 1); if (seg >= 1) s += t;
            t = __shfl_up_sync(0xFFFFFFFFu, s, 2); if (seg >= 2) s += t;
            int pos = s - pc;
            {
                unsigned int mw_[4] = {mm.x, mm.y, mm.z, mm.w};
#pragma unroll
                for (int w = 0; w < 4; w++) {
                    unsigned int m = mw_[w];
                    const int cb = seg * 128 + w * 32;
                    while (m) {
                        int j = __ffs((int)m) - 1;
                        m &= m - 1;
                        slT[pos * 8 + col] = (unsigned short)(cb + j);
                        pos++;
                    }
                }
            }
            // per-column count to every lane of that column; then warp max
            int c_cnt = __shfl_sync(0xFFFFFFFFu, s, (lane & 28) | 3);
            int cm = c_cnt;
#pragma unroll
            for (int off = 16; off > 0; off >>= 1) {
                int o = __shfl_xor_sync(0xFFFFFFFFu, cm, off);
                cm = (o > cm) ? o : cm;
            }
            for (int i = c_cnt + seg; i < cm; i += 4)
                slT[i * 8 + col] = 512;
            __syncwarp();

            // ---- Phase B: 8 interleaved chains, uniform count ----
            unsigned long long a0 = 0ULL, a1 = 0ULL, a2 = 0ULL, a3 = 0ULL;
            unsigned long long a4 = 0ULL, a5 = 0ULL, a6 = 0ULL, a7 = 0ULL;
#pragma unroll 2
            for (int i = 0; i < cm; i++) {
                uint4 p = *(const uint4*)&slT[i * 8];
                a0 = add2(a0, *(const unsigned long long*)&ws[((p.x & 0xFFFFu) << 6) + l2]);
                a1 = add2(a1, *(const unsigned long long*)&ws[((p.x >> 16) << 6) + l2]);
                a2 = add2(a2, *(const unsigned long long*)&ws[((p.y & 0xFFFFu) << 6) + l2]);
                a3 = add2(a3, *(const unsigned long long*)&ws[((p.y >> 16) << 6) + l2]);
                a4 = add2(a4, *(const unsigned long long*)&ws[((p.z & 0xFFFFu) << 6) + l2]);
                a5 = add2(a5, *(const unsigned long long*)&ws[((p.z >> 16) << 6) + l2]);
                a6 = add2(a6, *(const unsigned long long*)&ws[((p.w & 0xFFFFu) << 6) + l2]);
                a7 = add2(a7, *(const unsigned long long*)&ws[((p.w >> 16) << 6) + l2]);
            }
            unsigned long long accs[8] = {a0, a1, a2, a3, a4, a5, a6, a7};
#pragma unroll
            for (int i8 = 0; i8 < 8; i8++) {
                float ax, ay;
                asm("mov.b64 {%0, %1}, %2;" : "=f"(ax), "=f"(ay) : "l"(accs[i8]));
                ot[(l2 + 0) * 9 + i8] = ax;
                ot[(l2 + 1) * 9 + i8] = ay;
            }
            __syncwarp();
#pragma unroll
            for (int r = 0; r < 2; r++) {
                const int dl = lane + 32 * r;
                float4 v0 = make_float4(ot[dl * 9 + 0], ot[dl * 9 + 1],
                                        ot[dl * 9 + 2], ot[dl * 9 + 3]);
                float4 v1 = make_float4(ot[dl * 9 + 4], ot[dl * 9 + 5],
                                        ot[dl * 9 + 6], ot[dl * 9 + 7]);
                *(float4*)&Yb[(size_t)(d0 + dl) * N_ + n0] = v0;
                *(float4*)&Yb[(size_t)(d0 + dl) * N_ + n0 + 4] = v1;
            }
            __syncwarp();
        }
    }
}

// =============================================================================
// Dense conv (1x1 == GEMM), fp32 single ascending-c FFMA chain per output.
// FROZEN numerics. Used for the proj conv (xs is ~45% dense — sparse loses).
// =============================================================================
__global__ __launch_bounds__(256) void k_conv(const unsigned char* __restrict__ S,
                                              const float* __restrict__ W,
                                              const float* __restrict__ bias,
                                              float* __restrict__ Y) {
    __shared__ float sW[8][132];
    __shared__ float sS[8][132];
    const int tid = threadIdx.x;
    const int n0 = blockIdx.x * 128;
    const int d0 = blockIdx.y * 128;
    const size_t base = (size_t)blockIdx.z * CN_;
    const unsigned char* Sb = S + base;
    float* Yb = Y + base;

    const int tx4 = (tid & 15) * 4;
    const int ty4 = (tid >> 4) * 4;

    const int wrow = tid >> 1;
    const int wcol = (tid & 1) * 4;
    const int srow = tid >> 5;
    const int scol = (tid & 31) * 4;

    float acc[8][8];
#pragma unroll
    for (int i = 0; i < 8; i++)
#pragma unroll
        for (int j = 0; j < 8; j++) acc[i][j] = 0.0f;

    for (int k0 = 0; k0 < C_; k0 += 8) {
        float4 wv = *(const float4*)&W[(size_t)(d0 + wrow) * C_ + k0 + wcol];
        uchar4 sv = *(const uchar4*)&Sb[(size_t)(k0 + srow) * N_ + n0 + scol];
        __syncthreads();
        sW[wcol + 0][wrow] = wv.x;
        sW[wcol + 1][wrow] = wv.y;
        sW[wcol + 2][wrow] = wv.z;
        sW[wcol + 3][wrow] = wv.w;
        sS[srow][scol + 0] = (float)sv.x;
        sS[srow][scol + 1] = (float)sv.y;
        sS[srow][scol + 2] = (float)sv.z;
        sS[srow][scol + 3] = (float)sv.w;
        __syncthreads();
#pragma unroll
        for (int kk = 0; kk < 8; kk++) {
            float4 a0 = *(const float4*)&sW[kk][ty4];
            float4 a1 = *(const float4*)&sW[kk][ty4 + 64];
            float4 b0 = *(const float4*)&sS[kk][tx4];
            float4 b1 = *(const float4*)&sS[kk][tx4 + 64];
            float a[8] = {a0.x, a0.y, a0.z, a0.w, a1.x, a1.y, a1.z, a1.w};
            float b[8] = {b0.x, b0.y, b0.z, b0.w, b1.x, b1.y, b1.z, b1.w};
#pragma unroll
            for (int i = 0; i < 8; i++)
#pragma unroll
                for (int j = 0; j < 8; j++) acc[i][j] += a[i] * b[j];
        }
    }

#pragma unroll
    for (int qi = 0; qi < 2; qi++)
#pragma unroll
        for (int i = 0; i < 4; i++) {
            int d = d0 + qi * 64 + ty4 + i;
            float bs = bias ? bias[d] : 0.0f;
#pragma unroll
            for (int qj = 0; qj < 2; qj++) {
                float4 o;
                o.x = acc[qi * 4 + i][qj * 4 + 0] + bs;
                o.y = acc[qi * 4 + i][qj * 4 + 1] + bs;
                o.z = acc[qi * 4 + i][qj * 4 + 2] + bs;
                o.w = acc[qi * 4 + i][qj * 4 + 3] + bs;
                *(float4*)&Yb[(size_t)d * N_ + n0 + qj * 64 + tx4] = o;
            }
        }
}

// =============================================================================
// BatchNorm stats emulating the XLA-GPU vectorized row-reduction bitwise.
// FROZEN — this schedule produced rel_err = 0.0.
// =============================================================================
__device__ __forceinline__ float block_tree_sum(float acc, float* warp_part,
                                                int tid) {
    int lane = tid & 31, wid = tid >> 5;
#pragma unroll
    for (int off = 16; off > 0; off >>= 1)
        acc = __fadd_rn(acc, __shfl_down_sync(0xFFFFFFFFu, acc, off));
    if (lane == 0) warp_part[wid] = acc;
    __syncthreads();
    float v = 0.0f;
    if (wid == 0) {
        v = (lane < 16) ? warp_part[lane] : 0.0f;
#pragma unroll
        for (int off = 16; off > 0; off >>= 1)
            v = __fadd_rn(v, __shfl_down_sync(0xFFFFFFFFu, v, off));
    }
    return v;
}

__global__ __launch_bounds__(512) void k_stats(const float* __restrict__ Yq,
                                               const float* __restrict__ Yk,
                                               const float* __restrict__ Yv,
                                               int idx_base) {
    __shared__ float warp_part[16];
    __shared__ float s_mean;
    const int idx = idx_base + blockIdx.y;
    const float* Y = (blockIdx.y == 0) ? Yq : (blockIdx.y == 1) ? Yk : Yv;
    const int c = blockIdx.x;
    const int tid = threadIdx.x;
    const float* Yc = Y + (size_t)c * N_ + 2 * tid;

    float ax = 0.0f, ay = 0.0f;
    for (int b = 0; b < TB_; b++) {
        float2 v = *(const float2*)(Yc + (size_t)b * CN_);
        ax = __fadd_rn(ax, v.x);
        ay = __fadd_rn(ay, v.y);
    }
    float total = block_tree_sum(__fadd_rn(ax, ay), warp_part, tid);
    if (tid == 0)
        s_mean = __fmul_rn(total, 1.52587890625e-05f);
    __syncthreads();
    const float m = s_mean;
    __syncthreads();

    ax = 0.0f; ay = 0.0f;
    for (int b = 0; b < TB_; b++) {
        float2 v = *(const float2*)(Yc + (size_t)b * CN_);
        float dx = __fsub_rn(v.x, m);
        ax = __fadd_rn(ax, __fmul_rn(dx, dx));
        float dy = __fsub_rn(v.y, m);
        ay = __fadd_rn(ay, __fmul_rn(dy, dy));
    }
    float tv = block_tree_sum(__fadd_rn(ax, ay), warp_part, tid);
    if (tid == 0) {
        float var = __fmul_rn(tv, 1.52587890625e-05f);
        g_mean[idx * C_ + c] = m;
        g_rstd[idx * C_ + c] = rsqrtf(__fadd_rn(var, 1e-5f));
    }
}

// =============================================================================
// v path: BN(yv) inline, LIF with carried-over membrane state -> vs2 spikes
// =============================================================================
__global__ __launch_bounds__(256) void k_vlif(const float* __restrict__ gam,
                                              const float* __restrict__ bet) {
    size_t i = (size_t)blockIdx.x * 256 + threadIdx.x;
    if (i >= BCN_) return;
    int c = (int)((i >> 10) & (C_ - 1));
    float m = g_mean[2 * C_ + c], r = g_rstd[2 * C_ + c];
    float ga = gam[c], be = bet[c];
    float v = g_vst[i];
#pragma unroll
    for (int t = 0; t < T_; t++) {
        size_t off = (size_t)t * BCN_ + i;
        float y = __fadd_rn(__fmul_rn(__fmul_rn(__fsub_rn(g_yv[off], m), r), ga), be);
        v = lif_up(v, y);
        unsigned char s = (v >= 1.0f) ? 1 : 0;
        g_vs2[off] = s;
        if (s) v = 0.0f;
    }
}

// =============================================================================
// Fused linear attention + attn_lif. One block per (b,h), 512 threads in two
// groups (g = tid>>8). Phase 1: kv[t] for all 4 t (group g does t = g, g+2).
// Phase 2: per n-chunk, loop t with LIF membrane in registers, write xs.
// All arithmetic expressions identical to the unfused kernels -> bit-exact.
// =============================================================================
__global__ __launch_bounds__(512) void k_attn_fused(const float* __restrict__ qg,
                                                    const float* __restrict__ qbt,
                                                    const float* __restrict__ kg,
                                                    const float* __restrict__ kbt) {
    extern __shared__ float sm_at[];
    float* skv4 = sm_at;               // 4 x 64*68 = 17408 floats
    float* sbufb = sm_at + 4 * 4352;   // 2 groups x 4352 floats
    const int tid = threadIdx.x;
    const int g = tid >> 8;
    const int wg_tid = tid & 255;
    const int bx = blockIdx.x;
    const int b = bx >> 3, h = bx & 7;
    const int eg = (wg_tid & 15) * 4;
    const int dg = (wg_tid >> 4) * 4;
    float* sbuf = sbufb + g * 4352;

    // ---------------- phase 1: kv[t] ----------------
#pragma unroll
    for (int tt = 0; tt < 2; tt++) {
        const int t = g + tt * 2;
        const size_t base = (size_t)(t * B_ + b) * CN_ + (size_t)(h * 64) * N_;
        const float* Yk = g_yk + base;
        const unsigned char* V = g_vs2 + base;

        float acc[4][4];
#pragma unroll
        for (int i = 0; i < 4; i++)
#pragma unroll
            for (int j = 0; j < 4; j++) acc[i][j] = 0.0f;

        float* sK = sbuf;            // [d][33]
        float* sV = sbuf + 64 * 33;  // [e][33]
        for (int n0 = 0; n0 < N_; n0 += 32) {
            __syncthreads();
            for (int idx = wg_tid; idx < 2048; idx += 256) {
                int d = idx >> 5, n = idx & 31;
                int c = h * 64 + d;
                float mk = g_mean[C_ + c], rk = g_rstd[C_ + c];
                sK[d * 33 + n] = ((Yk[(size_t)d * N_ + n0 + n] - mk) * rk) * kg[c] + kbt[c];
                sV[d * 33 + n] = (float)V[(size_t)d * N_ + n0 + n];
            }
            __syncthreads();
#pragma unroll 8
            for (int n = 0; n < 32; n++) {
                float a0 = sK[(dg + 0) * 33 + n];
                float a1 = sK[(dg + 1) * 33 + n];
                float a2 = sK[(dg + 2) * 33 + n];
                float a3 = sK[(dg + 3) * 33 + n];
                float c0 = sV[(eg + 0) * 33 + n];
                float c1 = sV[(eg + 1) * 33 + n];
                float c2 = sV[(eg + 2) * 33 + n];
                float c3 = sV[(eg + 3) * 33 + n];
                acc[0][0] += a0 * c0; acc[0][1] += a0 * c1; acc[0][2] += a0 * c2; acc[0][3] += a0 * c3;
                acc[1][0] += a1 * c0; acc[1][1] += a1 * c1; acc[1][2] += a1 * c2; acc[1][3] += a1 * c3;
                acc[2][0] += a2 * c0; acc[2][1] += a2 * c1; acc[2][2] += a2 * c2; acc[2][3] += a2 * c3;
                acc[3][0] += a3 * c0; acc[3][1] += a3 * c1; acc[3][2] += a3 * c2; acc[3][3] += a3 * c3;
            }
        }
        __syncthreads();
        float* skv = skv4 + t * 4352;
#pragma unroll
        for (int i = 0; i < 4; i++)
#pragma unroll
            for (int j = 0; j < 4; j++) skv[(dg + i) * 68 + eg + j] = acc[i][j];
    }
    __syncthreads();

    // ---------------- phase 2: x + LIF + xs ----------------
    const size_t xbase0 = (size_t)b * CN_ + (size_t)(h * 64) * N_;
    for (int nc = g; nc < 16; nc += 2) {
        const int n0 = nc * 64;
        float v[4][4];
#pragma unroll
        for (int i = 0; i < 4; i++)
#pragma unroll
            for (int j = 0; j < 4; j++) v[i][j] = 0.0f;

#pragma unroll
        for (int t = 0; t < T_; t++) {
            const size_t base = (size_t)(t * B_ + b) * CN_ + (size_t)(h * 64) * N_;
            const float* Yq = g_yq + base;
            __syncthreads();
            for (int idx = wg_tid; idx < 4096; idx += 256) {
                int d = idx >> 6, n = idx & 63;
                int c = h * 64 + d;
                float mq = g_mean[c], rq = g_rstd[c];
                sbuf[d * 68 + n] = ((Yq[(size_t)d * N_ + n0 + n] - mq) * rq) * qg[c] + qbt[c];
            }
            __syncthreads();
            const float* skv = skv4 + t * 4352;
            float acc2[4][4];
#pragma unroll
            for (int i = 0; i < 4; i++)
#pragma unroll
                for (int j = 0; j < 4; j++) acc2[i][j] = 0.0f;
#pragma unroll 8
            for (int d = 0; d < 64; d++) {
                float4 qv = *(const float4*)&sbuf[d * 68 + eg];
                float k0v = skv[d * 68 + dg + 0];
                float k1v = skv[d * 68 + dg + 1];
                float k2v = skv[d * 68 + dg + 2];
                float k3v = skv[d * 68 + dg + 3];
                acc2[0][0] += k0v * qv.x; acc2[0][1] += k0v * qv.y; acc2[0][2] += k0v * qv.z; acc2[0][3] += k0v * qv.w;
                acc2[1][0] += k1v * qv.x; acc2[1][1] += k1v * qv.y; acc2[1][2] += k1v * qv.z; acc2[1][3] += k1v * qv.w;
                acc2[2][0] += k2v * qv.x; acc2[2][1] += k2v * qv.y; acc2[2][2] += k2v * qv.z; acc2[2][3] += k2v * qv.w;
                acc2[3][0] += k3v * qv.x; acc2[3][1] += k3v * qv.y; acc2[3][2] += k3v * qv.z; acc2[3][3] += k3v * qv.w;
            }
            unsigned char* Xs = g_xs + (size_t)t * BCN_ + xbase0;
#pragma unroll
            for (int i = 0; i < 4; i++) {
                unsigned char sb[4];
#pragma unroll
                for (int j = 0; j < 4; j++) {
                    float x = acc2[i][j] * 0.125f;
                    v[i][j] = lif_up(v[i][j], x);
                    unsigned char s = (v[i][j] >= 0.5f) ? 1 : 0;
                    sb[j] = s;
                    if (s) v[i][j] = 0.0f;
                }
                uchar4 o = make_uchar4(sb[0], sb[1], sb[2], sb[3]);
                *(uchar4*)&Xs[(size_t)(dg + i) * N_ + n0 + eg] = o;
            }
        }
    }
}

// =============================================================================
// final: BN(proj) inline, LIF thr=1.0, write float spikes to d_out
// =============================================================================
__global__ __launch_bounds__(256) void k_final(const float* __restrict__ gam,
                                               const float* __restrict__ bet,
                                               float* __restrict__ out) {
    size_t i = (size_t)blockIdx.x * 256 + threadIdx.x;
    if (i >= BCN_) return;
    int c = (int)((i >> 10) & (C_ - 1));
    float m = g_mean[3 * C_ + c], r = g_rstd[3 * C_ + c];
    float ga = gam[c], be = bet[c];
    float v = 0.0f;
#pragma unroll
    for (int t = 0; t < T_; t++) {
        size_t off = (size_t)t * BCN_ + i;
        float y = __fadd_rn(__fmul_rn(__fmul_rn(__fsub_rn(g_yv[off], m), r), ga), be);
        v = lif_up(v, y);
        unsigned char s = (v >= 1.0f) ? 1 : 0;
        out[off] = (float)s;
        if (s) v = 0.0f;
    }
}

// =============================================================================
// host
// =============================================================================
extern "C" void kernel_launch(void* const* d_in, const int* in_sizes, int n_in,
                              void* d_out, int out_size) {
    const float* q   = (const float*)d_in[0];
    const float* k   = (const float*)d_in[1];
    const float* Wq  = (const float*)d_in[2];
    const float* qg  = (const float*)d_in[3];
    const float* qb  = (const float*)d_in[4];
    const float* Wk  = (const float*)d_in[5];
    const float* kg  = (const float*)d_in[6];
    const float* kb  = (const float*)d_in[7];
    const float* Wv  = (const float*)d_in[8];
    const float* vg  = (const float*)d_in[9];
    const float* vb  = (const float*)d_in[10];
    const float* Wp  = (const float*)d_in[11];
    const float* Wpb = (const float*)d_in[12];
    const float* pg  = (const float*)d_in[13];
    const float* pb  = (const float*)d_in[14];
    float* out = (float*)d_out;

    void *p_xs, *p_yq, *p_yk, *p_yv, *p_Mq, *p_Mk;
    cudaGetSymbolAddress(&p_xs, g_xs);
    cudaGetSymbolAddress(&p_yq, g_yq);
    cudaGetSymbolAddress(&p_yk, g_yk);
    cudaGetSymbolAddress(&p_yv, g_yv);
    cudaGetSymbolAddress(&p_Mq, g_Mq);
    cudaGetSymbolAddress(&p_Mk, g_Mk);

    const int ew_blocks = (int)(BCN_ / 256);   // 32768
    dim3 gconv(N_ / 128, C_ / 128, TB_);       // dense proj conv
    dim3 gmask(N_ / 256, TB_);                 // (4, 64)
    dim3 gsp(8, 16, 3);                        // (dtile, tb-group, qkv)
    dim3 gstats3(C_, 3);
    dim3 gstats1(C_, 1);

    const int SP_SMEM = 513 * 64 * 4 + 16 * 576 * 4 + 16 * SL_ * 8 * 2;  // 211200
    const int AT_SMEM = (4 * 4352 + 2 * 4352) * 4;                        // 104448
    cudaFuncSetAttribute(k_conv_sp3, cudaFuncAttributeMaxDynamicSharedMemorySize,
                         SP_SMEM);
    cudaFuncSetAttribute(k_attn_fused, cudaFuncAttributeMaxDynamicSharedMemorySize,
                         AT_SMEM);

    k_lif_qk<<<ew_blocks, 256>>>(q, k);
    k_bitmask<<<gmask, 256>>>();
    k_conv_sp3<<<gsp, 512, SP_SMEM>>>((const unsigned int*)p_Mq,
                                      (const unsigned int*)p_Mk,
                                      Wq, Wk, Wv,
                                      (float*)p_yq, (float*)p_yk, (float*)p_yv);
    k_stats<<<gstats3, 512>>>((const float*)p_yq, (const float*)p_yk,
                              (const float*)p_yv, 0);
    k_vlif<<<ew_blocks, 256>>>(vg, vb);
    k_attn_fused<<<B_ * H_, 512, AT_SMEM>>>(qg, qb, kg, kb);
    k_conv<<<gconv, 256>>>((const unsigned char*)p_xs, Wp, Wpb, (float*)p_yv);
    k_stats<<<gstats1, 512>>>((const float*)p_yv, (const float*)p_yv,
                              (const float*)p_yv, 3);
    k_final<<<ew_blocks, 256>>>(pg, pb, out);
}